// round 15
// baseline (speedup 1.0000x reference)
#include <cuda_runtime.h>

// ---------------------------------------------------------------------------
// GMMNet, 2 pixels/thread, packed f32x2 (FFMA2).
// R15 = R14 (tanh sigmoids, folded weights, x-prefetch, rolled s-loop)
//     + persistent CTAs: grid = 304 (= 2 x 152 SMs), grid-stride over
//       pixel-pairs -> one wave, no wave transitions, no partial-wave tail.
// ---------------------------------------------------------------------------

typedef unsigned long long u64;

namespace {
constexpr int Bn = 4, Sn = 8, Cn = 3, Hn = 384, Wn = 384, Kn = 5, CKn = 15;
constexpr int HWn  = Hn * Wn;            // 147456
constexpr int NPIX = Bn * HWn;           // 589824
constexpr int HALF = NPIX / 2;           // 294912

constexpr int PI_W1 = 0,   PI_B1 = 50,  PI_W2 = 55,  PI_B2 = 80;
constexpr int MU_W1 = 85,  MU_B1 = 430, MU_W2 = 445, MU_B2 = 670;
constexpr int SG_W1 = 685, SG_B1 = 800, SG_W2 = 805, SG_B2 = 830;
constexpr int GA_W1 = 835, GA_B1 = 860, GA_W2 = 865, GA_B2 = 870;
constexpr int NWTS  = 871;

constexpr float L2E = 1.4426950408889634f;

constexpr int NCTA = 304;                // 2 CTAs x 152 SMs (GB300)
constexpr int NTHR = 256;
}

__constant__ u64 cw2[NWTS];
__device__   u64 g_staging[NWTS];

// ---- packed helpers ---------------------------------------------------------
__device__ __forceinline__ u64 pk(float lo, float hi) {
    u64 r; asm("mov.b64 %0, {%1, %2};" : "=l"(r) : "f"(lo), "f"(hi)); return r;
}
__device__ __forceinline__ void upk(u64 v, float& lo, float& hi) {
    asm("mov.b64 {%0, %1}, %2;" : "=f"(lo), "=f"(hi) : "l"(v));
}
__device__ __forceinline__ u64 fma2(u64 a, u64 b, u64 c) {
    u64 d; asm("fma.rn.f32x2 %0, %1, %2, %3;" : "=l"(d) : "l"(a), "l"(b), "l"(c)); return d;
}
__device__ __forceinline__ u64 mul2(u64 a, u64 b) {
    u64 d; asm("mul.rn.f32x2 %0, %1, %2;" : "=l"(d) : "l"(a), "l"(b)); return d;
}
__device__ __forceinline__ u64 add2(u64 a, u64 b) {
    u64 d; asm("add.rn.f32x2 %0, %1, %2;" : "=l"(d) : "l"(a), "l"(b)); return d;
}
__device__ __forceinline__ float ex2f(float x) {
    float y; asm("ex2.approx.f32 %0, %1;" : "=f"(y) : "f"(x)); return y;
}
__device__ __forceinline__ float rcpf(float x) {
    float y; asm("rcp.approx.f32 %0, %1;" : "=f"(y) : "f"(x)); return y;
}
__device__ __forceinline__ float tanhf_a(float x) {
    float y; asm("tanh.approx.f32 %0, %1;" : "=f"(y) : "f"(x)); return y;
}
__device__ __forceinline__ u64 ex2_2(u64 x) {
    float lo, hi; upk(x, lo, hi); return pk(ex2f(lo), ex2f(hi));
}
__device__ __forceinline__ u64 rcp_2(u64 x) {
    float lo, hi; upk(x, lo, hi); return pk(rcpf(lo), rcpf(hi));
}
__device__ __forceinline__ u64 tanh_2(u64 x) {
    float lo, hi; upk(x, lo, hi); return pk(tanhf_a(lo), tanhf_a(hi));
}
__device__ __forceinline__ u64 relu2(u64 x) {
    float lo, hi; upk(x, lo, hi);
    return pk(fmaxf(lo, 0.f), fmaxf(hi, 0.f));
}
__device__ __forceinline__ u64 min0_2(u64 x) {
    float lo, hi; upk(x, lo, hi);
    return pk(fminf(lo, 0.f), fminf(hi, 0.f));
}

// ---- weight duplication + constant folding -----------------------------------
struct WPtrs { const float* p[16]; };

__global__ void dup_weights(WPtrs w) {
    const int i = blockIdx.x * blockDim.x + threadIdx.x;
    if (i >= NWTS) return;
    constexpr int off[17] = {PI_W1, PI_B1, PI_W2, PI_B2,
                             MU_W1, MU_B1, MU_W2, MU_B2,
                             SG_W1, SG_B1, SG_W2, SG_B2,
                             GA_W1, GA_B1, GA_W2, GA_B2, NWTS};
    int s = 0;
#pragma unroll
    for (int k = 1; k < 16; k++) if (i >= off[k]) s = k;
    float v = w.p[s][i - off[s]];
    if (s == 2 || s == 3)        v *=  L2E;    // PI_W2, PI_B2  (softmax exp->ex2)
    else if (s == 6 || s == 7)   v *=  0.5f;   // MU_W2, MU_B2  (sigmoid via tanh)
    else if (s == 10 || s == 11) v *= -L2E;    // SG_W2, SG_B2  (exp(-relu)->ex2 min0)
    else if (s == 14 || s == 15) v *=  0.5f;   // GA_W2, GA_B2  (sigmoid via tanh)
    g_staging[i] = pk(v, v);
}

// ---- main kernel --------------------------------------------------------------
__global__ void __launch_bounds__(256)
gmm2_kernel(const float* __restrict__ frames,   // [B,S,C,H,W]
            const float* __restrict__ mu0,      // [B,CK,H,W]
            float* __restrict__ out)            // [B,S,1,H,W]
{
    const u64 HALF2  = pk(0.5f, 0.5f);
    const u64 NEG12  = pk(-1.0f, -1.0f);
    const u64 C02    = pk(0.06349363593424097f, 0.06349363593424097f);   // (2pi)^-1.5
    const u64 NHL2E2 = pk(-0.7213475204444817f, -0.7213475204444817f);   // -0.5*log2e

    // persistent grid-stride over pixel-pairs
    for (int t = blockIdx.x * blockDim.x + threadIdx.x; t < HALF;
         t += NCTA * NTHR) {

        const int b0 = t / HWn,  hw0 = t - b0 * HWn;
        const int p1 = t + HALF;
        const int b1 = p1 / HWn, hw1 = p1 - b1 * HWn;

        const float* f0 = frames + (b0 * Sn * Cn) * HWn + hw0;
        const float* f1 = frames + (b1 * Sn * Cn) * HWn + hw1;
        const float* m0 = mu0 + (b0 * CKn) * HWn + hw0;
        const float* m1 = mu0 + (b1 * CKn) * HWn + hw1;
        float* o0 = out + (b0 * Sn) * HWn + hw0;
        float* o1 = out + (b1 * Sn) * HWn + hw1;

        // carried state: pi, mu, r2s = -0.5*log2e/sigma^2, cf = C0/sigma^3
        u64 pi[Kn], mu[CKn], r2s[Kn], cf[Kn];
#pragma unroll
        for (int k = 0; k < Kn; k++) { pi[k] = pk(0.2f, 0.2f); r2s[k] = NHL2E2; cf[k] = C02; }
#pragma unroll
        for (int i = 0; i < CKn; i++) mu[i] = pk(m0[i * HWn], m1[i * HWn]);

        // prefetch frame 0 x
        u64 x[Cn];
#pragma unroll
        for (int c = 0; c < Cn; c++)
            x[c] = pk(f0[c * HWn], f1[c * HWn]);

#pragma unroll 1
        for (int s = 0; s < Sn; s++) {
            // issue next frame's loads immediately (clamped)
            const int sn = (s + 1 < Sn) ? s + 1 : s;
            u64 xn[Cn];
#pragma unroll
            for (int c = 0; c < Cn; c++)
                xn[c] = pk(f0[(sn * Cn + c) * HWn], f1[(sn * Cn + c) * HWn]);

            // ---- density 1, alpha, rho ------------------------------------
            u64 alpha[Kn], rho[Kn];
#pragma unroll
            for (int k = 0; k < Kn; k++) {
                u64 t0 = fma2(mu[k * Cn + 0], NEG12, x[0]);
                u64 d  = mul2(t0, t0);
                u64 t1 = fma2(mu[k * Cn + 1], NEG12, x[1]);
                d = fma2(t1, t1, d);
                u64 t2 = fma2(mu[k * Cn + 2], NEG12, x[2]);
                d = fma2(t2, t2, d);
                const u64 dens = mul2(cf[k], ex2_2(mul2(d, r2s[k])));
                alpha[k] = mul2(pi[k], dens);
                rho[k]   = mul2(alpha[k], dens);
            }

            // ---- pi MLP -> softmax (W2 pre-scaled by log2e) -----------------
            u64 hp[Kn];
#pragma unroll
            for (int o = 0; o < Kn; o++) {
                u64 a = cw2[PI_B1 + o];
#pragma unroll
                for (int i = 0; i < Kn; i++) a = fma2(cw2[PI_W1 + o * 10 + i],     pi[i],    a);
#pragma unroll
                for (int i = 0; i < Kn; i++) a = fma2(cw2[PI_W1 + o * 10 + 5 + i], alpha[i], a);
                hp[o] = relu2(a);
            }
            u64 pin[Kn], esum = 0ULL;
#pragma unroll
            for (int o = 0; o < Kn; o++) {
                u64 a = cw2[PI_B2 + o];
#pragma unroll
                for (int i = 0; i < Kn; i++) a = fma2(cw2[PI_W2 + o * 5 + i], hp[i], a);
                pin[o] = ex2_2(a);
                esum   = add2(esum, pin[o]);
            }
            {
                const u64 einv = rcp_2(esum);
#pragma unroll
                for (int k = 0; k < Kn; k++) pin[k] = mul2(pin[k], einv);
            }

            // ---- mu MLP -> sigmoid via tanh (W2 pre-scaled by 0.5) ----------
            u64 hm[CKn];
#pragma unroll
            for (int o = 0; o < CKn; o++) {
                const int base = MU_W1 + o * 23;
                u64 a = cw2[MU_B1 + o];
#pragma unroll
                for (int c = 0; c < Cn; c++)  a = fma2(cw2[base + c],      x[c],   a);
#pragma unroll
                for (int i = 0; i < CKn; i++) a = fma2(cw2[base + 3 + i],  mu[i],  a);
#pragma unroll
                for (int i = 0; i < Kn; i++)  a = fma2(cw2[base + 18 + i], rho[i], a);
                hm[o] = relu2(a);
            }
            u64 mun[CKn];
#pragma unroll
            for (int o = 0; o < CKn; o++) {
                u64 a = cw2[MU_B2 + o];
#pragma unroll
                for (int i = 0; i < CKn; i++) a = fma2(cw2[MU_W2 + o * 15 + i], hm[i], a);
                mun[o] = fma2(tanh_2(a), HALF2, HALF2);   // sigmoid
            }

            // ---- sigma MLP (W2 pre-scaled by -log2e) ------------------------
            u64 hs[Kn];
#pragma unroll
            for (int o = 0; o < Kn; o++) {
                const int base = SG_W1 + o * 23;
                u64 a = cw2[SG_B1 + o];
#pragma unroll
                for (int c = 0; c < Cn; c++)  a = fma2(cw2[base + c],      x[c],   a);
#pragma unroll
                for (int i = 0; i < CKn; i++) a = fma2(cw2[base + 3 + i],  mun[i], a);
#pragma unroll
                for (int i = 0; i < Kn; i++)  a = fma2(cw2[base + 18 + i], rho[i], a);
                hs[o] = relu2(a);
            }
#pragma unroll
            for (int o = 0; o < Kn; o++) {
                u64 a = cw2[SG_B2 + o];
#pragma unroll
                for (int i = 0; i < Kn; i++) a = fma2(cw2[SG_W2 + o * 5 + i], hs[i], a);
                const u64 rin = ex2_2(min0_2(a));       // 1/sigma
                const u64 rr  = mul2(rin, rin);         // 1/sigma^2
                r2s[o] = mul2(rr, NHL2E2);
                cf[o]  = mul2(mul2(rin, C02), rr);      // C0/sigma^3
            }

            // ---- density 2, g = pi_new * dens2 ------------------------------
            u64 g[Kn];
#pragma unroll
            for (int k = 0; k < Kn; k++) {
                u64 t0 = fma2(mun[k * Cn + 0], NEG12, x[0]);
                u64 d  = mul2(t0, t0);
                u64 t1 = fma2(mun[k * Cn + 1], NEG12, x[1]);
                d = fma2(t1, t1, d);
                u64 t2 = fma2(mun[k * Cn + 2], NEG12, x[2]);
                d = fma2(t2, t2, d);
                g[k] = mul2(pin[k], mul2(cf[k], ex2_2(mul2(d, r2s[k]))));
            }

            // ---- gamma MLP -> sigmoid via tanh (W2/B2 pre-scaled by 0.5) -----
            u64 hg[Kn];
#pragma unroll
            for (int o = 0; o < Kn; o++) {
                u64 a = cw2[GA_B1 + o];
#pragma unroll
                for (int i = 0; i < Kn; i++) a = fma2(cw2[GA_W1 + o * 5 + i], g[i], a);
                hg[o] = relu2(a);
            }
            u64 ga = cw2[GA_B2];
#pragma unroll
            for (int i = 0; i < Kn; i++) ga = fma2(cw2[GA_W2 + i], hg[i], ga);
            {
                float al, ah; upk(ga, al, ah);
                o0[s * HWn] = fmaf(tanhf_a(al), 0.5f, 0.5f);
                o1[s * HWn] = fmaf(tanhf_a(ah), 0.5f, 0.5f);
            }

            // ---- carry + buffer swap ------------------------------------------
#pragma unroll
            for (int k = 0; k < Kn; k++)  pi[k] = pin[k];
#pragma unroll
            for (int i = 0; i < CKn; i++) mu[i] = mun[i];
#pragma unroll
            for (int c = 0; c < Cn; c++)  x[c] = xn[c];
        }
    }
}

extern "C" void kernel_launch(void* const* d_in, const int* in_sizes, int n_in,
                              void* d_out, int out_size)
{
    (void)in_sizes; (void)n_in; (void)out_size;
    const float* frames = (const float*)d_in[0];
    const float* mu0    = (const float*)d_in[2];   // d_in[1] = targets (unused)

    WPtrs w;
    for (int i = 0; i < 16; i++) w.p[i] = (const float*)d_in[3 + i];

    dup_weights<<<4, 256>>>(w);

    void* staging_addr = nullptr;
    cudaGetSymbolAddress(&staging_addr, g_staging);
    cudaMemcpyToSymbolAsync(cw2, staging_addr, NWTS * sizeof(u64), 0,
                            cudaMemcpyDeviceToDevice, 0);

    gmm2_kernel<<<NCTA, NTHR>>>(frames, mu0, (float*)d_out);
}

// round 16
// speedup vs baseline: 1.0376x; 1.0376x over previous
#include <cuda_runtime.h>

// ---------------------------------------------------------------------------
// GMMNet, 2 pixels/thread, packed f32x2 (FFMA2).
// R16 = R14 champion (tanh sigmoids, folded weights, x-prefetch, rolled
// s-loop, 256 thr/1152 CTA waves) + carry-MOV elimination:
//   - softmax writes pi[] in place (pi dead after pi-L1)
//   - mu-sigmoid writes mu[] in place (mu dead after mu-L1)
// ---------------------------------------------------------------------------

typedef unsigned long long u64;

namespace {
constexpr int Bn = 4, Sn = 8, Cn = 3, Hn = 384, Wn = 384, Kn = 5, CKn = 15;
constexpr int HWn  = Hn * Wn;            // 147456
constexpr int NPIX = Bn * HWn;           // 589824
constexpr int HALF = NPIX / 2;           // 294912

constexpr int PI_W1 = 0,   PI_B1 = 50,  PI_W2 = 55,  PI_B2 = 80;
constexpr int MU_W1 = 85,  MU_B1 = 430, MU_W2 = 445, MU_B2 = 670;
constexpr int SG_W1 = 685, SG_B1 = 800, SG_W2 = 805, SG_B2 = 830;
constexpr int GA_W1 = 835, GA_B1 = 860, GA_W2 = 865, GA_B2 = 870;
constexpr int NWTS  = 871;

constexpr float L2E = 1.4426950408889634f;
}

__constant__ u64 cw2[NWTS];
__device__   u64 g_staging[NWTS];

// ---- packed helpers ---------------------------------------------------------
__device__ __forceinline__ u64 pk(float lo, float hi) {
    u64 r; asm("mov.b64 %0, {%1, %2};" : "=l"(r) : "f"(lo), "f"(hi)); return r;
}
__device__ __forceinline__ void upk(u64 v, float& lo, float& hi) {
    asm("mov.b64 {%0, %1}, %2;" : "=f"(lo), "=f"(hi) : "l"(v));
}
__device__ __forceinline__ u64 fma2(u64 a, u64 b, u64 c) {
    u64 d; asm("fma.rn.f32x2 %0, %1, %2, %3;" : "=l"(d) : "l"(a), "l"(b), "l"(c)); return d;
}
__device__ __forceinline__ u64 mul2(u64 a, u64 b) {
    u64 d; asm("mul.rn.f32x2 %0, %1, %2;" : "=l"(d) : "l"(a), "l"(b)); return d;
}
__device__ __forceinline__ u64 add2(u64 a, u64 b) {
    u64 d; asm("add.rn.f32x2 %0, %1, %2;" : "=l"(d) : "l"(a), "l"(b)); return d;
}
__device__ __forceinline__ float ex2f(float x) {
    float y; asm("ex2.approx.f32 %0, %1;" : "=f"(y) : "f"(x)); return y;
}
__device__ __forceinline__ float rcpf(float x) {
    float y; asm("rcp.approx.f32 %0, %1;" : "=f"(y) : "f"(x)); return y;
}
__device__ __forceinline__ float tanhf_a(float x) {
    float y; asm("tanh.approx.f32 %0, %1;" : "=f"(y) : "f"(x)); return y;
}
__device__ __forceinline__ u64 ex2_2(u64 x) {
    float lo, hi; upk(x, lo, hi); return pk(ex2f(lo), ex2f(hi));
}
__device__ __forceinline__ u64 rcp_2(u64 x) {
    float lo, hi; upk(x, lo, hi); return pk(rcpf(lo), rcpf(hi));
}
__device__ __forceinline__ u64 tanh_2(u64 x) {
    float lo, hi; upk(x, lo, hi); return pk(tanhf_a(lo), tanhf_a(hi));
}
__device__ __forceinline__ u64 relu2(u64 x) {
    float lo, hi; upk(x, lo, hi);
    return pk(fmaxf(lo, 0.f), fmaxf(hi, 0.f));
}
__device__ __forceinline__ u64 min0_2(u64 x) {
    float lo, hi; upk(x, lo, hi);
    return pk(fminf(lo, 0.f), fminf(hi, 0.f));
}

// ---- weight duplication + constant folding -----------------------------------
struct WPtrs { const float* p[16]; };

__global__ void dup_weights(WPtrs w) {
    const int i = blockIdx.x * blockDim.x + threadIdx.x;
    if (i >= NWTS) return;
    constexpr int off[17] = {PI_W1, PI_B1, PI_W2, PI_B2,
                             MU_W1, MU_B1, MU_W2, MU_B2,
                             SG_W1, SG_B1, SG_W2, SG_B2,
                             GA_W1, GA_B1, GA_W2, GA_B2, NWTS};
    int s = 0;
#pragma unroll
    for (int k = 1; k < 16; k++) if (i >= off[k]) s = k;
    float v = w.p[s][i - off[s]];
    if (s == 2 || s == 3)        v *=  L2E;    // PI_W2, PI_B2  (softmax exp->ex2)
    else if (s == 6 || s == 7)   v *=  0.5f;   // MU_W2, MU_B2  (sigmoid via tanh)
    else if (s == 10 || s == 11) v *= -L2E;    // SG_W2, SG_B2  (exp(-relu)->ex2 min0)
    else if (s == 14 || s == 15) v *=  0.5f;   // GA_W2, GA_B2  (sigmoid via tanh)
    g_staging[i] = pk(v, v);
}

// ---- main kernel --------------------------------------------------------------
__global__ void __launch_bounds__(256)
gmm2_kernel(const float* __restrict__ frames,   // [B,S,C,H,W]
            const float* __restrict__ mu0,      // [B,CK,H,W]
            float* __restrict__ out)            // [B,S,1,H,W]
{
    const int t = blockIdx.x * blockDim.x + threadIdx.x;
    if (t >= HALF) return;

    const int b0 = t / HWn,  hw0 = t - b0 * HWn;
    const int p1 = t + HALF;
    const int b1 = p1 / HWn, hw1 = p1 - b1 * HWn;

    const float* f0 = frames + (b0 * Sn * Cn) * HWn + hw0;
    const float* f1 = frames + (b1 * Sn * Cn) * HWn + hw1;
    const float* m0 = mu0 + (b0 * CKn) * HWn + hw0;
    const float* m1 = mu0 + (b1 * CKn) * HWn + hw1;
    float* o0 = out + (b0 * Sn) * HWn + hw0;
    float* o1 = out + (b1 * Sn) * HWn + hw1;

    const u64 HALF2  = pk(0.5f, 0.5f);
    const u64 NEG12  = pk(-1.0f, -1.0f);
    const u64 C02    = pk(0.06349363593424097f, 0.06349363593424097f);   // (2pi)^-1.5
    const u64 NHL2E2 = pk(-0.7213475204444817f, -0.7213475204444817f);   // -0.5*log2e

    // carried state: pi, mu, r2s = -0.5*log2e/sigma^2, cf = C0/sigma^3
    u64 pi[Kn], mu[CKn], r2s[Kn], cf[Kn];
#pragma unroll
    for (int k = 0; k < Kn; k++) { pi[k] = pk(0.2f, 0.2f); r2s[k] = NHL2E2; cf[k] = C02; }
#pragma unroll
    for (int i = 0; i < CKn; i++) mu[i] = pk(m0[i * HWn], m1[i * HWn]);

    // prefetch frame 0 x
    u64 x[Cn];
#pragma unroll
    for (int c = 0; c < Cn; c++)
        x[c] = pk(f0[c * HWn], f1[c * HWn]);

#pragma unroll 1
    for (int s = 0; s < Sn; s++) {
        // issue next frame's loads immediately (clamped; full frame to cover)
        const int sn = (s + 1 < Sn) ? s + 1 : s;
        u64 xn[Cn];
#pragma unroll
        for (int c = 0; c < Cn; c++)
            xn[c] = pk(f0[(sn * Cn + c) * HWn], f1[(sn * Cn + c) * HWn]);

        // ---- density 1, alpha, rho ---------------------------------------
        u64 alpha[Kn], rho[Kn];
#pragma unroll
        for (int k = 0; k < Kn; k++) {
            u64 t0 = fma2(mu[k * Cn + 0], NEG12, x[0]);
            u64 d  = mul2(t0, t0);
            u64 t1 = fma2(mu[k * Cn + 1], NEG12, x[1]);
            d = fma2(t1, t1, d);
            u64 t2 = fma2(mu[k * Cn + 2], NEG12, x[2]);
            d = fma2(t2, t2, d);
            const u64 dens = mul2(cf[k], ex2_2(mul2(d, r2s[k])));
            alpha[k] = mul2(pi[k], dens);
            rho[k]   = mul2(alpha[k], dens);
        }

        // ---- pi MLP -> softmax (W2 pre-scaled by log2e); writes pi in place
        u64 hp[Kn];
#pragma unroll
        for (int o = 0; o < Kn; o++) {
            u64 a = cw2[PI_B1 + o];
#pragma unroll
            for (int i = 0; i < Kn; i++) a = fma2(cw2[PI_W1 + o * 10 + i],     pi[i],    a);
#pragma unroll
            for (int i = 0; i < Kn; i++) a = fma2(cw2[PI_W1 + o * 10 + 5 + i], alpha[i], a);
            hp[o] = relu2(a);
        }
        // pi[] dead after layer 1 above -> overwrite with new softmax values
        u64 esum = 0ULL;
#pragma unroll
        for (int o = 0; o < Kn; o++) {
            u64 a = cw2[PI_B2 + o];
#pragma unroll
            for (int i = 0; i < Kn; i++) a = fma2(cw2[PI_W2 + o * 5 + i], hp[i], a);
            pi[o] = ex2_2(a);
            esum  = add2(esum, pi[o]);
        }
        {
            const u64 einv = rcp_2(esum);
#pragma unroll
            for (int k = 0; k < Kn; k++) pi[k] = mul2(pi[k], einv);
        }

        // ---- mu MLP -> sigmoid via tanh (W2 pre-scaled by 0.5) --------------
        u64 hm[CKn];
#pragma unroll
        for (int o = 0; o < CKn; o++) {
            const int base = MU_W1 + o * 23;
            u64 a = cw2[MU_B1 + o];
#pragma unroll
            for (int c = 0; c < Cn; c++)  a = fma2(cw2[base + c],      x[c],   a);
#pragma unroll
            for (int i = 0; i < CKn; i++) a = fma2(cw2[base + 3 + i],  mu[i],  a);
#pragma unroll
            for (int i = 0; i < Kn; i++)  a = fma2(cw2[base + 18 + i], rho[i], a);
            hm[o] = relu2(a);
        }
        // mu[] dead after layer 1 above -> overwrite with mun in place
#pragma unroll
        for (int o = 0; o < CKn; o++) {
            u64 a = cw2[MU_B2 + o];
#pragma unroll
            for (int i = 0; i < CKn; i++) a = fma2(cw2[MU_W2 + o * 15 + i], hm[i], a);
            mu[o] = fma2(tanh_2(a), HALF2, HALF2);   // sigmoid -> new mu
        }

        // ---- sigma MLP (W2 pre-scaled by -log2e): rinv = ex2(min(a',0)) ----
        u64 hs[Kn];
#pragma unroll
        for (int o = 0; o < Kn; o++) {
            const int base = SG_W1 + o * 23;
            u64 a = cw2[SG_B1 + o];
#pragma unroll
            for (int c = 0; c < Cn; c++)  a = fma2(cw2[base + c],      x[c],  a);
#pragma unroll
            for (int i = 0; i < CKn; i++) a = fma2(cw2[base + 3 + i],  mu[i], a);   // mu == mun
#pragma unroll
            for (int i = 0; i < Kn; i++)  a = fma2(cw2[base + 18 + i], rho[i], a);
            hs[o] = relu2(a);
        }
#pragma unroll
        for (int o = 0; o < Kn; o++) {
            u64 a = cw2[SG_B2 + o];
#pragma unroll
            for (int i = 0; i < Kn; i++) a = fma2(cw2[SG_W2 + o * 5 + i], hs[i], a);
            const u64 rin = ex2_2(min0_2(a));       // 1/sigma
            const u64 rr  = mul2(rin, rin);         // 1/sigma^2
            r2s[o] = mul2(rr, NHL2E2);
            cf[o]  = mul2(mul2(rin, C02), rr);      // C0/sigma^3
        }

        // ---- density 2 (mu == mun), g = pi_new * dens2 -----------------------
        u64 g[Kn];
#pragma unroll
        for (int k = 0; k < Kn; k++) {
            u64 t0 = fma2(mu[k * Cn + 0], NEG12, x[0]);
            u64 d  = mul2(t0, t0);
            u64 t1 = fma2(mu[k * Cn + 1], NEG12, x[1]);
            d = fma2(t1, t1, d);
            u64 t2 = fma2(mu[k * Cn + 2], NEG12, x[2]);
            d = fma2(t2, t2, d);
            g[k] = mul2(pi[k], mul2(cf[k], ex2_2(mul2(d, r2s[k]))));
        }

        // ---- gamma MLP -> sigmoid via tanh (W2/B2 pre-scaled by 0.5) ---------
        u64 hg[Kn];
#pragma unroll
        for (int o = 0; o < Kn; o++) {
            u64 a = cw2[GA_B1 + o];
#pragma unroll
            for (int i = 0; i < Kn; i++) a = fma2(cw2[GA_W1 + o * 5 + i], g[i], a);
            hg[o] = relu2(a);
        }
        u64 ga = cw2[GA_B2];
#pragma unroll
        for (int i = 0; i < Kn; i++) ga = fma2(cw2[GA_W2 + i], hg[i], ga);
        {
            float al, ah; upk(ga, al, ah);
            o0[s * HWn] = fmaf(tanhf_a(al), 0.5f, 0.5f);
            o1[s * HWn] = fmaf(tanhf_a(ah), 0.5f, 0.5f);
        }

        // ---- buffer swap (only x remains to carry) ----------------------------
#pragma unroll
        for (int c = 0; c < Cn; c++) x[c] = xn[c];
    }
}

extern "C" void kernel_launch(void* const* d_in, const int* in_sizes, int n_in,
                              void* d_out, int out_size)
{
    (void)in_sizes; (void)n_in; (void)out_size;
    const float* frames = (const float*)d_in[0];
    const float* mu0    = (const float*)d_in[2];   // d_in[1] = targets (unused)

    WPtrs w;
    for (int i = 0; i < 16; i++) w.p[i] = (const float*)d_in[3 + i];

    dup_weights<<<4, 256>>>(w);

    void* staging_addr = nullptr;
    cudaGetSymbolAddress(&staging_addr, g_staging);
    cudaMemcpyToSymbolAsync(cw2, staging_addr, NWTS * sizeof(u64), 0,
                            cudaMemcpyDeviceToDevice, 0);

    const int threads = 256;
    const int blocks  = HALF / threads;   // 1152
    gmm2_kernel<<<blocks, threads>>>(frames, mu0, (float*)d_out);
}